// round 1
// baseline (speedup 1.0000x reference)
#include <cuda_runtime.h>

#define D_DIM 2048
#define B_TOK 4096

// Scratch (device globals — no allocation allowed)
__device__ float g_tv[(size_t)B_TOK * D_DIM];
__device__ float g_lv[(size_t)B_TOK * D_DIM];
__device__ float g_qv[(size_t)B_TOK * D_DIM];
__device__ float g_err[(size_t)B_TOK * D_DIM];
__device__ float g_Wnew[(size_t)D_DIM * D_DIM];
__device__ float g_bnew[D_DIM];
__device__ float g_part[32 * D_DIM];

// ---------------------------------------------------------------------------
// Generic tiled SGEMM: C[M,N] = op(A) * op(B) with fused epilogues.
// TA==0: A is [M,K] row-major.  TA==1: A is [K,M] row-major (TN gemm).
// TB==0: B is [K,N] row-major.  TB==1: B is [N,K] row-major (NT gemm).
// EPI 0: C = acc
// EPI 1: C = acc + e0[n] + e1[idx] - e2[idx]          (err = pred + b + tv - lv)
// EPI 2: C = e1[idx] - e2[idx] * (coef * acc)          (W_new = W - lr_w*gW)
// EPI 3: C = acc + e0[n] + e1[idx]                     (z = qv@Wnew^T + bnew + qv)
// All dims are multiples of 128 (K multiple of 8) -> no bounds checks.
// ---------------------------------------------------------------------------
template <int TA, int TB, int EPI>
__global__ __launch_bounds__(256, 2)
void sgemm_kernel(const float* __restrict__ A, const float* __restrict__ B,
                  float* __restrict__ C, int M, int N, int K,
                  const float* __restrict__ e0, const float* __restrict__ e1,
                  const float* __restrict__ e2, float coef)
{
    constexpr int BM = 128, BN = 128, BK = 8;

    __shared__ float As[2][BK][BM];
    __shared__ float Bs[2][BK][BN];

    const int tid = threadIdx.x;         // 0..255
    const int tx  = tid & 15;            // 0..15
    const int ty  = tid >> 4;            // 0..15
    const int m0  = blockIdx.y * BM;
    const int n0  = blockIdx.x * BN;

    // Global-load pointers and per-K-tile steps
    const float* aPtr;
    const float* bPtr;
    size_t aStep, bStep;
    if (TA == 0) {
        aPtr  = A + (size_t)(m0 + (tid >> 1)) * K + ((tid & 1) << 2);
        aStep = BK;
    } else {
        aPtr  = A + (size_t)(tid >> 5) * M + m0 + ((tid & 31) << 2);
        aStep = (size_t)BK * M;
    }
    if (TB == 0) {
        bPtr  = B + (size_t)(tid >> 5) * N + n0 + ((tid & 31) << 2);
        bStep = (size_t)BK * N;
    } else {
        bPtr  = B + (size_t)(n0 + (tid >> 1)) * K + ((tid & 1) << 2);
        bStep = BK;
    }

    float4 aReg, bReg;

    // prologue: tile 0
    aReg = *reinterpret_cast<const float4*>(aPtr); aPtr += aStep;
    bReg = *reinterpret_cast<const float4*>(bPtr); bPtr += bStep;

    // store tile 0 into smem[0]
    {
        if (TA == 0) {
            int r = tid >> 1, c = (tid & 1) << 2;
            As[0][c + 0][r] = aReg.x; As[0][c + 1][r] = aReg.y;
            As[0][c + 2][r] = aReg.z; As[0][c + 3][r] = aReg.w;
        } else {
            *reinterpret_cast<float4*>(&As[0][tid >> 5][(tid & 31) << 2]) = aReg;
        }
        if (TB == 0) {
            *reinterpret_cast<float4*>(&Bs[0][tid >> 5][(tid & 31) << 2]) = bReg;
        } else {
            int r = tid >> 1, c = (tid & 1) << 2;
            Bs[0][c + 0][r] = bReg.x; Bs[0][c + 1][r] = bReg.y;
            Bs[0][c + 2][r] = bReg.z; Bs[0][c + 3][r] = bReg.w;
        }
    }
    __syncthreads();

    float acc[8][8];
#pragma unroll
    for (int i = 0; i < 8; ++i)
#pragma unroll
        for (int j = 0; j < 8; ++j) acc[i][j] = 0.0f;

    const int nt = K / BK;
    for (int t = 0; t < nt; ++t) {
        const int buf = t & 1;

        // prefetch next tile into registers (latency hidden by compute)
        if (t + 1 < nt) {
            aReg = *reinterpret_cast<const float4*>(aPtr); aPtr += aStep;
            bReg = *reinterpret_cast<const float4*>(bPtr); bPtr += bStep;
        }

        // compute this tile
#pragma unroll
        for (int kk = 0; kk < BK; ++kk) {
            float4 a0 = *reinterpret_cast<const float4*>(&As[buf][kk][ty << 2]);
            float4 a1 = *reinterpret_cast<const float4*>(&As[buf][kk][(ty << 2) + 64]);
            float4 b0 = *reinterpret_cast<const float4*>(&Bs[buf][kk][tx << 2]);
            float4 b1 = *reinterpret_cast<const float4*>(&Bs[buf][kk][(tx << 2) + 64]);
            float av[8] = {a0.x, a0.y, a0.z, a0.w, a1.x, a1.y, a1.z, a1.w};
            float bv[8] = {b0.x, b0.y, b0.z, b0.w, b1.x, b1.y, b1.z, b1.w};
#pragma unroll
            for (int i = 0; i < 8; ++i)
#pragma unroll
                for (int j = 0; j < 8; ++j)
                    acc[i][j] += av[i] * bv[j];
        }

        // stash next tile into the other buffer
        if (t + 1 < nt) {
            const int nb = (t + 1) & 1;
            if (TA == 0) {
                int r = tid >> 1, c = (tid & 1) << 2;
                As[nb][c + 0][r] = aReg.x; As[nb][c + 1][r] = aReg.y;
                As[nb][c + 2][r] = aReg.z; As[nb][c + 3][r] = aReg.w;
            } else {
                *reinterpret_cast<float4*>(&As[nb][tid >> 5][(tid & 31) << 2]) = aReg;
            }
            if (TB == 0) {
                *reinterpret_cast<float4*>(&Bs[nb][tid >> 5][(tid & 31) << 2]) = bReg;
            } else {
                int r = tid >> 1, c = (tid & 1) << 2;
                Bs[nb][c + 0][r] = bReg.x; Bs[nb][c + 1][r] = bReg.y;
                Bs[nb][c + 2][r] = bReg.z; Bs[nb][c + 3][r] = bReg.w;
            }
            __syncthreads();
        }
    }

    // epilogue: 8 rows x 2 float4 per thread
#pragma unroll
    for (int ii = 0; ii < 8; ++ii) {
        int r = m0 + ((ii < 4) ? (ty << 2) + ii : (ty << 2) + 64 + (ii - 4));
#pragma unroll
        for (int jj = 0; jj < 2; ++jj) {
            int c = n0 + (tx << 2) + jj * 64;
            size_t idx = (size_t)r * N + c;
            float4 v;
            v.x = acc[ii][jj * 4 + 0];
            v.y = acc[ii][jj * 4 + 1];
            v.z = acc[ii][jj * 4 + 2];
            v.w = acc[ii][jj * 4 + 3];
            if (EPI == 1) {
                float4 t1 = *reinterpret_cast<const float4*>(e1 + idx);
                float4 t2 = *reinterpret_cast<const float4*>(e2 + idx);
                v.x += e0[c + 0] + t1.x - t2.x;
                v.y += e0[c + 1] + t1.y - t2.y;
                v.z += e0[c + 2] + t1.z - t2.z;
                v.w += e0[c + 3] + t1.w - t2.w;
            } else if (EPI == 2) {
                float4 w  = *reinterpret_cast<const float4*>(e1 + idx);
                float4 lr = *reinterpret_cast<const float4*>(e2 + idx);
                v.x = w.x - lr.x * (coef * v.x);
                v.y = w.y - lr.y * (coef * v.y);
                v.z = w.z - lr.z * (coef * v.z);
                v.w = w.w - lr.w * (coef * v.w);
            } else if (EPI == 3) {
                float4 q = *reinterpret_cast<const float4*>(e1 + idx);
                v.x += e0[c + 0] + q.x;
                v.y += e0[c + 1] + q.y;
                v.z += e0[c + 2] + q.z;
                v.w += e0[c + 3] + q.w;
            }
            *reinterpret_cast<float4*>(C + idx) = v;
        }
    }
}

// Partial column sums of err: part[chunk][col] = sum over 128 rows
__global__ void colsum_kernel(const float* __restrict__ err, float* __restrict__ part)
{
    int col = blockIdx.x * blockDim.x + threadIdx.x;  // 0..2047
    int chunk = blockIdx.y;                           // 0..31
    const float* p = err + (size_t)chunk * 128 * D_DIM + col;
    float s0 = 0.f, s1 = 0.f, s2 = 0.f, s3 = 0.f;
#pragma unroll
    for (int r = 0; r < 128; r += 4) {
        s0 += p[(size_t)(r + 0) * D_DIM];
        s1 += p[(size_t)(r + 1) * D_DIM];
        s2 += p[(size_t)(r + 2) * D_DIM];
        s3 += p[(size_t)(r + 3) * D_DIM];
    }
    part[chunk * D_DIM + col] = (s0 + s1) + (s2 + s3);
}

// b_new = b - lr_b * coef * gb
__global__ void bnew_kernel(const float* __restrict__ part, const float* __restrict__ b,
                            const float* __restrict__ lr_b, float* __restrict__ bn, float coef)
{
    int j = blockIdx.x * blockDim.x + threadIdx.x;
    float s = 0.f;
#pragma unroll
    for (int c = 0; c < 32; ++c) s += part[c * D_DIM + j];
    bn[j] = b[j] - lr_b[j] * (coef * s);
}

extern "C" void kernel_launch(void* const* d_in, const int* in_sizes, int n_in,
                              void* d_out, int out_size)
{
    const float* src  = (const float*)d_in[0];
    const float* th_k = (const float*)d_in[1];
    const float* th_q = (const float*)d_in[2];
    const float* th_v = (const float*)d_in[3];
    const float* W    = (const float*)d_in[4];
    const float* b    = (const float*)d_in[5];
    const float* lr_w = (const float*)d_in[6];
    const float* lr_b = (const float*)d_in[7];
    float* out = (float*)d_out;

    float *tv, *lv, *qv, *err, *Wn, *bn, *part;
    cudaGetSymbolAddress((void**)&tv,   g_tv);
    cudaGetSymbolAddress((void**)&lv,   g_lv);
    cudaGetSymbolAddress((void**)&qv,   g_qv);
    cudaGetSymbolAddress((void**)&err,  g_err);
    cudaGetSymbolAddress((void**)&Wn,   g_Wnew);
    cudaGetSymbolAddress((void**)&bn,   g_bnew);
    cudaGetSymbolAddress((void**)&part, g_part);

    const float coef = 2.0f / ((float)B_TOK * (float)D_DIM);

    dim3 gridBig(D_DIM / 128, B_TOK / 128);   // (16, 32)
    dim3 gridSq(D_DIM / 128, D_DIM / 128);    // (16, 16)

    // Projections: tv/qv/lv = src @ theta_{k,q,v}
    sgemm_kernel<0, 0, 0><<<gridBig, 256>>>(src, th_k, tv, B_TOK, D_DIM, D_DIM,
                                            nullptr, nullptr, nullptr, 0.f);
    sgemm_kernel<0, 0, 0><<<gridBig, 256>>>(src, th_q, qv, B_TOK, D_DIM, D_DIM,
                                            nullptr, nullptr, nullptr, 0.f);
    sgemm_kernel<0, 0, 0><<<gridBig, 256>>>(src, th_v, lv, B_TOK, D_DIM, D_DIM,
                                            nullptr, nullptr, nullptr, 0.f);

    // err = tv @ W^T + b + tv - lv
    sgemm_kernel<0, 1, 1><<<gridBig, 256>>>(tv, W, err, B_TOK, D_DIM, D_DIM,
                                            b, tv, lv, 0.f);

    // gb / b_new
    colsum_kernel<<<dim3(D_DIM / 256, 32), 256>>>(err, part);
    bnew_kernel<<<D_DIM / 256, 256>>>(part, b, lr_b, bn, coef);

    // W_new = W - lr_w * (coef * err^T @ tv)   (TN gemm, K = B_TOK)
    sgemm_kernel<1, 0, 2><<<gridSq, 256>>>(err, tv, Wn, D_DIM, D_DIM, B_TOK,
                                           nullptr, W, lr_w, coef);

    // z = qv @ W_new^T + b_new + qv
    sgemm_kernel<0, 1, 3><<<gridBig, 256>>>(qv, Wn, out, B_TOK, D_DIM, D_DIM,
                                            bn, qv, nullptr, 0.f);
}

// round 2
// speedup vs baseline: 2.4336x; 2.4336x over previous
#include <cuda_runtime.h>
#include <cstdint>

#define D_DIM 2048
#define B_TOK 4096

// Scratch (device globals — no allocation allowed)
__device__ float g_tv[(size_t)B_TOK * D_DIM];
__device__ float g_lv[(size_t)B_TOK * D_DIM];
__device__ float g_qv[(size_t)B_TOK * D_DIM];
__device__ float g_err[(size_t)B_TOK * D_DIM];
__device__ float g_Wnew[(size_t)D_DIM * D_DIM];
__device__ float g_bnew[D_DIM];
__device__ float g_part[32 * D_DIM];

__device__ __forceinline__ uint32_t f2tf(float x) {
    uint32_t r;
    asm("cvt.rna.tf32.f32 %0, %1;" : "=r"(r) : "f"(x));
    return r;
}

__device__ __forceinline__ void cp16(uint32_t dst, const float* src) {
    asm volatile("cp.async.cg.shared.global [%0], [%1], 16;" :: "r"(dst), "l"(src));
}

__device__ __forceinline__ void mma_tf32(float c[4], const uint32_t a[4], const uint32_t b[2]) {
    asm volatile(
        "mma.sync.aligned.m16n8k8.row.col.f32.tf32.tf32.f32 "
        "{%0,%1,%2,%3}, {%4,%5,%6,%7}, {%8,%9}, {%0,%1,%2,%3};"
        : "+f"(c[0]), "+f"(c[1]), "+f"(c[2]), "+f"(c[3])
        : "r"(a[0]), "r"(a[1]), "r"(a[2]), "r"(a[3]), "r"(b[0]), "r"(b[1]));
}

// ---------------------------------------------------------------------------
// tf32 tensor-core GEMM: C[M,N] = op(A)*op(B), fused epilogues.
// TA==0: A [M,K] row-major.  TA==1: A [K,M] row-major (TN).
// TB==0: B [K,N] row-major (NN).  TB==1: B [N,K] row-major (NT).
// EPI 0: C = acc
// EPI 1: C = acc + e0[n] + e1[idx] - e2[idx]
// EPI 2: C = e1[idx] - e2[idx] * (coef * acc)
// EPI 3: C = acc + e0[n] + e1[idx]
// Tiles: CTA 128x128x32, 8 warps of 64x32, m16n8k8 frags.
// SMEM tiles stored in natural global orientation (cp.async 16B), orientation
// resolved at fragment-load time. Row strides 36/136 => conflict-free LDS.
// ---------------------------------------------------------------------------
template <int TA, int TB, int EPI>
__global__ void __launch_bounds__(256)
tgemm(const float* __restrict__ A, const float* __restrict__ B,
      float* __restrict__ C, int M, int N, int K,
      const float* __restrict__ e0, const float* __restrict__ e1,
      const float* __restrict__ e2, float coef)
{
    constexpr int BK  = 32;
    constexpr int SA  = (TA == 0) ? 36 : 136;        // A tile row stride (floats)
    constexpr int SB  = (TB == 0) ? 136 : 36;        // B tile row stride
    constexpr int ASZ = (TA == 0) ? 128 * 36 : 32 * 136;
    constexpr int BSZ = (TB == 0) ? 32 * 136 : 128 * 36;

    extern __shared__ float sm[];
    float* Asm = sm;
    float* Bsm = sm + 3 * ASZ;

    const int tid  = threadIdx.x;
    const int lane = tid & 31;
    const int wid  = tid >> 5;
    const int g    = lane >> 2;
    const int tig  = lane & 3;
    const int wm   = (wid & 1) * 64;
    const int wn   = (wid >> 1) * 32;
    const int m0   = blockIdx.y * 128;
    const int n0   = blockIdx.x * 128;

    const uint32_t sbase = (uint32_t)__cvta_generic_to_shared(sm);

    auto issue = [&](int t) {
        const int kt = t * BK;
        const int stage = t % 3;
        const uint32_t aBase = sbase + (uint32_t)(stage * ASZ) * 4u;
        const uint32_t bBase = sbase + (uint32_t)(3 * ASZ + stage * BSZ) * 4u;
#pragma unroll
        for (int i = 0; i < 4; ++i) {
            const int q = tid + i * 256;
            if (TA == 0) {
                const int r = q >> 3, c4 = q & 7;
                cp16(aBase + (uint32_t)(r * SA + c4 * 4) * 4u,
                     A + (size_t)(m0 + r) * K + kt + c4 * 4);
            } else {
                const int r = q >> 5, c4 = q & 31;
                cp16(aBase + (uint32_t)(r * SA + c4 * 4) * 4u,
                     A + (size_t)(kt + r) * M + m0 + c4 * 4);
            }
            if (TB == 0) {
                const int r = q >> 5, c4 = q & 31;
                cp16(bBase + (uint32_t)(r * SB + c4 * 4) * 4u,
                     B + (size_t)(kt + r) * N + n0 + c4 * 4);
            } else {
                const int r = q >> 3, c4 = q & 7;
                cp16(bBase + (uint32_t)(r * SB + c4 * 4) * 4u,
                     B + (size_t)(n0 + r) * K + kt + c4 * 4);
            }
        }
        asm volatile("cp.async.commit_group;");
    };

    float acc[4][4][4];
#pragma unroll
    for (int i = 0; i < 4; ++i)
#pragma unroll
        for (int j = 0; j < 4; ++j)
#pragma unroll
            for (int k = 0; k < 4; ++k) acc[i][j][k] = 0.0f;

    const int nt = K / BK;
    issue(0);
    issue(1);

    for (int t = 0; t < nt; ++t) {
        if (t + 1 < nt) asm volatile("cp.async.wait_group 1;");
        else            asm volatile("cp.async.wait_group 0;");
        __syncthreads();
        if (t + 2 < nt) issue(t + 2);

        const int stage = t % 3;
        const float* As = Asm + stage * ASZ;
        const float* Bs = Bsm + stage * BSZ;
        const float* pA = (TA == 0) ? As + (wm + g) * 36 + tig
                                    : As + tig * 136 + wm + g;
        const float* pB = (TB == 0) ? Bs + tig * 136 + wn + g
                                    : Bs + (wn + g) * 36 + tig;

#pragma unroll
        for (int kk = 0; kk < 4; ++kk) {
            uint32_t bf[4][2];
#pragma unroll
            for (int nf = 0; nf < 4; ++nf) {
                if (TB == 0) {
                    bf[nf][0] = f2tf(pB[(kk * 8)     * 136 + nf * 8]);
                    bf[nf][1] = f2tf(pB[(kk * 8 + 4) * 136 + nf * 8]);
                } else {
                    bf[nf][0] = f2tf(pB[nf * 8 * 36 + kk * 8]);
                    bf[nf][1] = f2tf(pB[nf * 8 * 36 + kk * 8 + 4]);
                }
            }
            uint32_t af[4][4];
#pragma unroll
            for (int mf = 0; mf < 4; ++mf) {
                if (TA == 0) {
                    af[mf][0] = f2tf(pA[(mf * 16)     * 36 + kk * 8]);
                    af[mf][1] = f2tf(pA[(mf * 16 + 8) * 36 + kk * 8]);
                    af[mf][2] = f2tf(pA[(mf * 16)     * 36 + kk * 8 + 4]);
                    af[mf][3] = f2tf(pA[(mf * 16 + 8) * 36 + kk * 8 + 4]);
                } else {
                    af[mf][0] = f2tf(pA[(kk * 8)     * 136 + mf * 16]);
                    af[mf][1] = f2tf(pA[(kk * 8)     * 136 + mf * 16 + 8]);
                    af[mf][2] = f2tf(pA[(kk * 8 + 4) * 136 + mf * 16]);
                    af[mf][3] = f2tf(pA[(kk * 8 + 4) * 136 + mf * 16 + 8]);
                }
            }
#pragma unroll
            for (int mf = 0; mf < 4; ++mf)
#pragma unroll
                for (int nf = 0; nf < 4; ++nf)
                    mma_tf32(acc[mf][nf], af[mf], bf[nf]);
        }
    }

    // Epilogue: per (mf,nf) frag, two float2 rows
#pragma unroll
    for (int mf = 0; mf < 4; ++mf) {
#pragma unroll
        for (int nf = 0; nf < 4; ++nf) {
#pragma unroll
            for (int h = 0; h < 2; ++h) {
                const int r = m0 + wm + mf * 16 + g + h * 8;
                const int c = n0 + wn + nf * 8 + 2 * tig;
                const size_t idx = (size_t)r * N + c;
                float v0 = acc[mf][nf][h * 2 + 0];
                float v1 = acc[mf][nf][h * 2 + 1];
                if (EPI == 1) {
                    const float2 t1 = *reinterpret_cast<const float2*>(e1 + idx);
                    const float2 t2 = *reinterpret_cast<const float2*>(e2 + idx);
                    v0 += e0[c]     + t1.x - t2.x;
                    v1 += e0[c + 1] + t1.y - t2.y;
                } else if (EPI == 2) {
                    const float2 w  = *reinterpret_cast<const float2*>(e1 + idx);
                    const float2 lr = *reinterpret_cast<const float2*>(e2 + idx);
                    v0 = w.x - lr.x * (coef * v0);
                    v1 = w.y - lr.y * (coef * v1);
                } else if (EPI == 3) {
                    const float2 q = *reinterpret_cast<const float2*>(e1 + idx);
                    v0 += e0[c]     + q.x;
                    v1 += e0[c + 1] + q.y;
                }
                float2 out;
                out.x = v0; out.y = v1;
                *reinterpret_cast<float2*>(C + idx) = out;
            }
        }
    }
}

// Partial column sums of err: part[chunk][col] = sum over 128 rows
__global__ void colsum_kernel(const float* __restrict__ err, float* __restrict__ part)
{
    int col = blockIdx.x * blockDim.x + threadIdx.x;
    int chunk = blockIdx.y;
    const float* p = err + (size_t)chunk * 128 * D_DIM + col;
    float s0 = 0.f, s1 = 0.f, s2 = 0.f, s3 = 0.f;
#pragma unroll
    for (int r = 0; r < 128; r += 4) {
        s0 += p[(size_t)(r + 0) * D_DIM];
        s1 += p[(size_t)(r + 1) * D_DIM];
        s2 += p[(size_t)(r + 2) * D_DIM];
        s3 += p[(size_t)(r + 3) * D_DIM];
    }
    part[chunk * D_DIM + col] = (s0 + s1) + (s2 + s3);
}

__global__ void bnew_kernel(const float* __restrict__ part, const float* __restrict__ b,
                            const float* __restrict__ lr_b, float* __restrict__ bn, float coef)
{
    int j = blockIdx.x * blockDim.x + threadIdx.x;
    float s = 0.f;
#pragma unroll
    for (int c = 0; c < 32; ++c) s += part[c * D_DIM + j];
    bn[j] = b[j] - lr_b[j] * (coef * s);
}

extern "C" void kernel_launch(void* const* d_in, const int* in_sizes, int n_in,
                              void* d_out, int out_size)
{
    const float* src  = (const float*)d_in[0];
    const float* th_k = (const float*)d_in[1];
    const float* th_q = (const float*)d_in[2];
    const float* th_v = (const float*)d_in[3];
    const float* W    = (const float*)d_in[4];
    const float* b    = (const float*)d_in[5];
    const float* lr_w = (const float*)d_in[6];
    const float* lr_b = (const float*)d_in[7];
    float* out = (float*)d_out;

    float *tv, *lv, *qv, *err, *Wn, *bn, *part;
    cudaGetSymbolAddress((void**)&tv,   g_tv);
    cudaGetSymbolAddress((void**)&lv,   g_lv);
    cudaGetSymbolAddress((void**)&qv,   g_qv);
    cudaGetSymbolAddress((void**)&err,  g_err);
    cudaGetSymbolAddress((void**)&Wn,   g_Wnew);
    cudaGetSymbolAddress((void**)&bn,   g_bnew);
    cudaGetSymbolAddress((void**)&part, g_part);

    const float coef = 2.0f / ((float)B_TOK * (float)D_DIM);

    // Dynamic smem sizes (3-stage double... triple buffers)
    const int S_NN = 3 * (128 * 36 + 32 * 136) * 4;   // 107520
    const int S_NT = 3 * (128 * 36 + 128 * 36) * 4;   // 110592
    const int S_TN = 3 * (32 * 136 + 32 * 136) * 4;   // 104448

    cudaFuncSetAttribute(tgemm<0, 0, 0>, cudaFuncAttributeMaxDynamicSharedMemorySize, S_NN);
    cudaFuncSetAttribute(tgemm<0, 1, 1>, cudaFuncAttributeMaxDynamicSharedMemorySize, S_NT);
    cudaFuncSetAttribute(tgemm<1, 0, 2>, cudaFuncAttributeMaxDynamicSharedMemorySize, S_TN);
    cudaFuncSetAttribute(tgemm<0, 1, 3>, cudaFuncAttributeMaxDynamicSharedMemorySize, S_NT);

    dim3 gridBig(D_DIM / 128, B_TOK / 128);   // (16, 32)
    dim3 gridSq(D_DIM / 128, D_DIM / 128);    // (16, 16)

    // Projections: tv/qv/lv = src @ theta_{k,q,v}   (NN)
    tgemm<0, 0, 0><<<gridBig, 256, S_NN>>>(src, th_k, tv, B_TOK, D_DIM, D_DIM,
                                           nullptr, nullptr, nullptr, 0.f);
    tgemm<0, 0, 0><<<gridBig, 256, S_NN>>>(src, th_q, qv, B_TOK, D_DIM, D_DIM,
                                           nullptr, nullptr, nullptr, 0.f);
    tgemm<0, 0, 0><<<gridBig, 256, S_NN>>>(src, th_v, lv, B_TOK, D_DIM, D_DIM,
                                           nullptr, nullptr, nullptr, 0.f);

    // err = tv @ W^T + b + tv - lv   (NT)
    tgemm<0, 1, 1><<<gridBig, 256, S_NT>>>(tv, W, err, B_TOK, D_DIM, D_DIM,
                                           b, tv, lv, 0.f);

    // gb / b_new
    colsum_kernel<<<dim3(D_DIM / 256, 32), 256>>>(err, part);
    bnew_kernel<<<D_DIM / 256, 256>>>(part, b, lr_b, bn, coef);

    // W_new = W - lr_w * (coef * err^T @ tv)   (TN, K = B_TOK)
    tgemm<1, 0, 2><<<gridSq, 256, S_TN>>>(err, tv, Wn, D_DIM, D_DIM, B_TOK,
                                          nullptr, W, lr_w, coef);

    // z = qv @ W_new^T + b_new + qv   (NT)
    tgemm<0, 1, 3><<<gridBig, 256, S_NT>>>(qv, Wn, out, B_TOK, D_DIM, D_DIM,
                                           bn, qv, nullptr, 0.f);
}

// round 4
// speedup vs baseline: 3.9682x; 1.6306x over previous
#include <cuda_runtime.h>
#include <cstdint>

#define D_DIM 2048
#define B_TOK 4096

// ---------------- scratch (device globals; no allocation allowed) ----------
__device__ float g_srcR[(size_t)B_TOK * D_DIM];
__device__ float g_srcT[(size_t)B_TOK * D_DIM];
__device__ float g_thkR[(size_t)D_DIM * D_DIM];
__device__ float g_thqR[(size_t)D_DIM * D_DIM];
__device__ float g_WR  [(size_t)D_DIM * D_DIM];
__device__ float g_thkT[(size_t)D_DIM * D_DIM];
__device__ float g_S   [(size_t)D_DIM * D_DIM];
__device__ float g_M   [(size_t)D_DIM * D_DIM];
__device__ float g_T1  [(size_t)D_DIM * D_DIM];
__device__ float g_MT  [(size_t)D_DIM * D_DIM];
__device__ float g_T1T [(size_t)D_DIM * D_DIM];
__device__ float g_Wn  [(size_t)D_DIM * D_DIM];
__device__ float g_P   [(size_t)D_DIM * D_DIM];
__device__ float g_PT  [(size_t)D_DIM * D_DIM];
__device__ float g_part[32 * D_DIM];
__device__ float g_c   [D_DIM];
__device__ float g_v   [D_DIM];
__device__ float g_bn  [D_DIM];

// ---------------- PTX helpers ----------------------------------------------
__device__ __forceinline__ float rnd_tf32(float x) {
    uint32_t r;
    asm("cvt.rna.tf32.f32 %0, %1;" : "=r"(r) : "f"(x));
    return __uint_as_float(r);
}

__device__ __forceinline__ void cp16(uint32_t dst, const float* src) {
    asm volatile("cp.async.cg.shared.global [%0], [%1], 16;" :: "r"(dst), "l"(src));
}

__device__ __forceinline__ void ldsm4(uint32_t& r0, uint32_t& r1, uint32_t& r2, uint32_t& r3,
                                      uint32_t addr) {
    asm volatile("ldmatrix.sync.aligned.m8n8.x4.shared.b16 {%0,%1,%2,%3}, [%4];"
                 : "=r"(r0), "=r"(r1), "=r"(r2), "=r"(r3) : "r"(addr));
}

__device__ __forceinline__ void mma_tf32(float c[4], const uint32_t a[4],
                                         uint32_t b0, uint32_t b1) {
    asm volatile(
        "mma.sync.aligned.m16n8k8.row.col.f32.tf32.tf32.f32 "
        "{%0,%1,%2,%3}, {%4,%5,%6,%7}, {%8,%9}, {%0,%1,%2,%3};"
        : "+f"(c[0]), "+f"(c[1]), "+f"(c[2]), "+f"(c[3])
        : "r"(a[0]), "r"(a[1]), "r"(a[2]), "r"(a[3]), "r"(b0), "r"(b1));
}

// ---------------------------------------------------------------------------
// NT tf32 tensor GEMM:  C[M,N] = A[M,K] * B[N,K]^T  (+ fused epilogues)
// Inputs MUST be pre-rounded to tf32 (RNA) — mainloop has no cvt.
// CTA 128x128, BK=32, 3-stage cp.async, 8 warps of 64x32, ldmatrix frag loads.
// EPI 0: C = acc
// EPI 1: C = acc + e1[idx] - e2[idx]
// EPI 2: C = e1[idx] - e2[idx] * coef * (acc + ev0[row]*ev1[col])
// EPI 3: C = acc + e1[idx]
// EPI 4: C = acc + e0[col]
// ---------------------------------------------------------------------------
template <int EPI, bool RND>
__global__ void __launch_bounds__(256)
ntgemm(const float* __restrict__ A, const float* __restrict__ B,
       float* __restrict__ C, int M, int N, int K,
       const float* __restrict__ e0, const float* __restrict__ e1,
       const float* __restrict__ e2, const float* __restrict__ ev0,
       const float* __restrict__ ev1, float coef)
{
    constexpr int BK   = 32;
    constexpr int TILE = 128 * BK * 4;   // 16 KB per operand tile
    constexpr int SS   = 2 * TILE;       // 32 KB per stage

    extern __shared__ __align__(128) char smraw[];
    const uint32_t sb = (uint32_t)__cvta_generic_to_shared(smraw);

    const int tid  = threadIdx.x;
    const int lane = tid & 31;
    const int wid  = tid >> 5;
    const int wm   = (wid & 1) * 64;
    const int wn   = (wid >> 1) * 32;
    const int m0   = blockIdx.y * 128;
    const int n0   = blockIdx.x * 128;

    // ---- global->smem loader mapping (XOR-swizzled 16B chunks) ----
    const int lr = tid >> 3;            // 0..31 (row base; +32*i)
    const int lc = tid & 7;             // chunk 0..7
    const uint32_t lOff = (uint32_t)(lr * 128 + ((lc ^ (lr & 7)) << 4));
    const float* aG = A + (size_t)(m0 + lr) * K + lc * 4;
    const float* bG = B + (size_t)(n0 + lr) * K + lc * 4;

    auto loadTile = [&](int t) {
        const uint32_t base = sb + (uint32_t)((t % 3) * SS);
        const float* a = aG + (size_t)t * BK;
        const float* b = bG + (size_t)t * BK;
#pragma unroll
        for (int i = 0; i < 4; ++i)
            cp16(base + lOff + 4096u * i, a + (size_t)(32 * i) * K);
#pragma unroll
        for (int i = 0; i < 4; ++i)
            cp16(base + TILE + lOff + 4096u * i, b + (size_t)(32 * i) * K);
        asm volatile("cp.async.commit_group;" ::: "memory");
    };

    // ---- ldmatrix addressing (precomputed) ----
    const int rr  = lane & 7;
    const int loA = (lane >> 3) & 1;    // A row +8 select
    const int hiA = (lane >> 4) & 1;    // A chunk +1 select
    const int loB = (lane >> 4) & 1;    // B row +8 select
    const int hiB = (lane >> 3) & 1;    // B chunk +1 select
    const uint32_t swz = (uint32_t)rr << 4;

    uint32_t aRow[4], bRow[2];
#pragma unroll
    for (int mf = 0; mf < 4; ++mf)
        aRow[mf] = (uint32_t)((wm + mf * 16 + loA * 8 + rr) * 128);
#pragma unroll
    for (int nfp = 0; nfp < 2; ++nfp)
        bRow[nfp] = (uint32_t)((wn + nfp * 16 + loB * 8 + rr) * 128);

    float acc[4][4][4];
#pragma unroll
    for (int i = 0; i < 4; ++i)
#pragma unroll
        for (int j = 0; j < 4; ++j)
#pragma unroll
            for (int k = 0; k < 4; ++k) acc[i][j][k] = 0.0f;

    const int nt = K / BK;
    loadTile(0);
    loadTile(1);

    for (int t = 0; t < nt; ++t) {
        if (t + 1 < nt) asm volatile("cp.async.wait_group 1;" ::: "memory");
        else            asm volatile("cp.async.wait_group 0;" ::: "memory");
        __syncthreads();
        if (t + 2 < nt) loadTile(t + 2);

        const uint32_t stA = sb + (uint32_t)((t % 3) * SS);
        const uint32_t stB = stA + TILE;

#pragma unroll
        for (int kk = 0; kk < 4; ++kk) {
            const uint32_t ak = (((uint32_t)(2 * kk + hiA)) << 4) ^ swz;
            const uint32_t bk = (((uint32_t)(2 * kk + hiB)) << 4) ^ swz;
            uint32_t af[4][4];
#pragma unroll
            for (int mf = 0; mf < 4; ++mf)
                ldsm4(af[mf][0], af[mf][1], af[mf][2], af[mf][3], stA + aRow[mf] + ak);
            uint32_t bf[2][4];
#pragma unroll
            for (int nfp = 0; nfp < 2; ++nfp)
                ldsm4(bf[nfp][0], bf[nfp][1], bf[nfp][2], bf[nfp][3], stB + bRow[nfp] + bk);
#pragma unroll
            for (int mf = 0; mf < 4; ++mf)
#pragma unroll
                for (int nf = 0; nf < 4; ++nf)
                    mma_tf32(acc[mf][nf], af[mf],
                             bf[nf >> 1][(nf & 1) * 2], bf[nf >> 1][(nf & 1) * 2 + 1]);
        }
        __syncthreads();
    }

    // ---- epilogue ----
    const int g   = lane >> 2;
    const int tig = lane & 3;
#pragma unroll
    for (int mf = 0; mf < 4; ++mf) {
#pragma unroll
        for (int nf = 0; nf < 4; ++nf) {
#pragma unroll
            for (int h = 0; h < 2; ++h) {
                const int r = m0 + wm + mf * 16 + g + h * 8;
                const int c = n0 + wn + nf * 8 + 2 * tig;
                const size_t idx = (size_t)r * N + c;
                float v0 = acc[mf][nf][h * 2 + 0];
                float v1 = acc[mf][nf][h * 2 + 1];
                if (EPI == 1) {
                    const float2 a1 = *reinterpret_cast<const float2*>(e1 + idx);
                    const float2 a2 = *reinterpret_cast<const float2*>(e2 + idx);
                    v0 += a1.x - a2.x;
                    v1 += a1.y - a2.y;
                } else if (EPI == 2) {
                    const float2 w  = *reinterpret_cast<const float2*>(e1 + idx);
                    const float2 lr = *reinterpret_cast<const float2*>(e2 + idx);
                    const float bi  = ev0[r];
                    const float g0  = coef * (v0 + bi * ev1[c]);
                    const float g1  = coef * (v1 + bi * ev1[c + 1]);
                    v0 = w.x - lr.x * g0;
                    v1 = w.y - lr.y * g1;
                } else if (EPI == 3) {
                    const float2 a1 = *reinterpret_cast<const float2*>(e1 + idx);
                    v0 += a1.x;
                    v1 += a1.y;
                } else if (EPI == 4) {
                    v0 += e0[c];
                    v1 += e0[c + 1];
                }
                if (RND) { v0 = rnd_tf32(v0); v1 = rnd_tf32(v1); }
                float2 out; out.x = v0; out.y = v1;
                *reinterpret_cast<float2*>(C + idx) = out;
            }
        }
    }
}

// ---------------- small kernels ----------------------------------------------
__global__ void round_kernel(const float* __restrict__ in, float* __restrict__ out, int n4)
{
    int i = blockIdx.x * blockDim.x + threadIdx.x;
    if (i < n4) {
        float4 v = reinterpret_cast<const float4*>(in)[i];
        v.x = rnd_tf32(v.x); v.y = rnd_tf32(v.y);
        v.z = rnd_tf32(v.z); v.w = rnd_tf32(v.w);
        reinterpret_cast<float4*>(out)[i] = v;
    }
}

// out[c, r] = rnd(in[r, c]); in is [R, C]; grid (C/32, R/32), block (32, 8)
__global__ void transpose_round(const float* __restrict__ in, float* __restrict__ out,
                                int R, int C)
{
    __shared__ float tile[32][33];
    const int bx = blockIdx.x * 32, by = blockIdx.y * 32;
    const int x = threadIdx.x, y = threadIdx.y;
#pragma unroll
    for (int j = 0; j < 32; j += 8)
        tile[y + j][x] = in[(size_t)(by + y + j) * C + bx + x];
    __syncthreads();
#pragma unroll
    for (int j = 0; j < 32; j += 8)
        out[(size_t)(bx + y + j) * R + by + x] = rnd_tf32(tile[x][y + j]);
}

// partial column sums over 128-row chunks (src is [4096, 2048])
__global__ void colsum_kernel(const float* __restrict__ in, float* __restrict__ part)
{
    int col = blockIdx.x * blockDim.x + threadIdx.x;
    int chunk = blockIdx.y;
    const float* p = in + (size_t)chunk * 128 * D_DIM + col;
    float s0 = 0.f, s1 = 0.f, s2 = 0.f, s3 = 0.f;
#pragma unroll
    for (int r = 0; r < 128; r += 4) {
        s0 += p[(size_t)(r + 0) * D_DIM];
        s1 += p[(size_t)(r + 1) * D_DIM];
        s2 += p[(size_t)(r + 2) * D_DIM];
        s3 += p[(size_t)(r + 3) * D_DIM];
    }
    part[chunk * D_DIM + col] = (s0 + s1) + (s2 + s3);
}

__global__ void creduce_kernel(const float* __restrict__ part, float* __restrict__ c)
{
    int j = blockIdx.x * blockDim.x + threadIdx.x;
    float s = 0.f;
#pragma unroll
    for (int ch = 0; ch < 32; ++ch) s += part[ch * D_DIM + j];
    c[j] = s;
}

// outv[j] = sum_k vec[k] * Mat[k, j]
__global__ void vecmat_kernel(const float* __restrict__ vec, const float* __restrict__ Mat,
                              float* __restrict__ outv)
{
    int j = blockIdx.x * blockDim.x + threadIdx.x;
    float s0 = 0.f, s1 = 0.f, s2 = 0.f, s3 = 0.f;
#pragma unroll 4
    for (int k = 0; k < D_DIM; k += 4) {
        s0 += vec[k + 0] * Mat[(size_t)(k + 0) * D_DIM + j];
        s1 += vec[k + 1] * Mat[(size_t)(k + 1) * D_DIM + j];
        s2 += vec[k + 2] * Mat[(size_t)(k + 2) * D_DIM + j];
        s3 += vec[k + 3] * Mat[(size_t)(k + 3) * D_DIM + j];
    }
    outv[j] = (s0 + s1) + (s2 + s3);
}

// bn[j] = b[j] - lr_b[j] * coef * ( (c @ M)[j] + B_TOK * b[j] )
__global__ void bn_kernel(const float* __restrict__ Mm, const float* __restrict__ c,
                          const float* __restrict__ b, const float* __restrict__ lrb,
                          float* __restrict__ bn, float coef)
{
    int j = blockIdx.x * blockDim.x + threadIdx.x;
    float s0 = 0.f, s1 = 0.f, s2 = 0.f, s3 = 0.f;
#pragma unroll 4
    for (int k = 0; k < D_DIM; k += 4) {
        s0 += c[k + 0] * Mm[(size_t)(k + 0) * D_DIM + j];
        s1 += c[k + 1] * Mm[(size_t)(k + 1) * D_DIM + j];
        s2 += c[k + 2] * Mm[(size_t)(k + 2) * D_DIM + j];
        s3 += c[k + 3] * Mm[(size_t)(k + 3) * D_DIM + j];
    }
    float s = (s0 + s1) + (s2 + s3);
    bn[j] = b[j] - lrb[j] * coef * (s + (float)B_TOK * b[j]);
}

// ---------------- host --------------------------------------------------------
extern "C" void kernel_launch(void* const* d_in, const int* in_sizes, int n_in,
                              void* d_out, int out_size)
{
    const float* src  = (const float*)d_in[0];
    const float* th_k = (const float*)d_in[1];
    const float* th_q = (const float*)d_in[2];
    const float* th_v = (const float*)d_in[3];
    const float* W    = (const float*)d_in[4];
    const float* b    = (const float*)d_in[5];
    const float* lr_w = (const float*)d_in[6];
    const float* lr_b = (const float*)d_in[7];
    float* out = (float*)d_out;

    float *srcR, *srcT, *thkR, *thqR, *WR, *thkT, *S, *Mm, *T1, *MT, *T1T, *Wn, *P, *PT;
    float *part, *cvec, *vvec, *bn;
    cudaGetSymbolAddress((void**)&srcR, g_srcR);
    cudaGetSymbolAddress((void**)&srcT, g_srcT);
    cudaGetSymbolAddress((void**)&thkR, g_thkR);
    cudaGetSymbolAddress((void**)&thqR, g_thqR);
    cudaGetSymbolAddress((void**)&WR,   g_WR);
    cudaGetSymbolAddress((void**)&thkT, g_thkT);
    cudaGetSymbolAddress((void**)&S,    g_S);
    cudaGetSymbolAddress((void**)&Mm,   g_M);
    cudaGetSymbolAddress((void**)&T1,   g_T1);
    cudaGetSymbolAddress((void**)&MT,   g_MT);
    cudaGetSymbolAddress((void**)&T1T,  g_T1T);
    cudaGetSymbolAddress((void**)&Wn,   g_Wn);
    cudaGetSymbolAddress((void**)&P,    g_P);
    cudaGetSymbolAddress((void**)&PT,   g_PT);
    cudaGetSymbolAddress((void**)&part, g_part);
    cudaGetSymbolAddress((void**)&cvec, g_c);
    cudaGetSymbolAddress((void**)&vvec, g_v);
    cudaGetSymbolAddress((void**)&bn,   g_bn);

    const float coef = 2.0f / ((float)B_TOK * (float)D_DIM);
    const int SMEM = 3 * 2 * 128 * 32 * 4;   // 98304

    cudaFuncSetAttribute(ntgemm<0, true >, cudaFuncAttributeMaxDynamicSharedMemorySize, SMEM);
    cudaFuncSetAttribute(ntgemm<0, false>, cudaFuncAttributeMaxDynamicSharedMemorySize, SMEM);
    cudaFuncSetAttribute(ntgemm<1, true >, cudaFuncAttributeMaxDynamicSharedMemorySize, SMEM);
    cudaFuncSetAttribute(ntgemm<2, true >, cudaFuncAttributeMaxDynamicSharedMemorySize, SMEM);
    cudaFuncSetAttribute(ntgemm<3, false>, cudaFuncAttributeMaxDynamicSharedMemorySize, SMEM);
    cudaFuncSetAttribute(ntgemm<4, false>, cudaFuncAttributeMaxDynamicSharedMemorySize, SMEM);

    dim3 tb(32, 8);

    // prep: rounded copies + transposes (transpose_round also rounds)
    round_kernel<<<(B_TOK * D_DIM / 4 + 255) / 256, 256>>>(src, srcR, B_TOK * D_DIM / 4);
    round_kernel<<<(D_DIM * D_DIM / 4 + 255) / 256, 256>>>(th_k, thkR, D_DIM * D_DIM / 4);
    round_kernel<<<(D_DIM * D_DIM / 4 + 255) / 256, 256>>>(th_q, thqR, D_DIM * D_DIM / 4);
    round_kernel<<<(D_DIM * D_DIM / 4 + 255) / 256, 256>>>(W, WR, D_DIM * D_DIM / 4);
    transpose_round<<<dim3(D_DIM / 32, B_TOK / 32), tb>>>(src, srcT, B_TOK, D_DIM);
    transpose_round<<<dim3(D_DIM / 32, D_DIM / 32), tb>>>(th_k, thkT, D_DIM, D_DIM);

    // column sums of src -> c ; v = c @ theta_k
    colsum_kernel<<<dim3(D_DIM / 256, 32), 256>>>(src, part);
    creduce_kernel<<<D_DIM / 256, 256>>>(part, cvec);
    vecmat_kernel<<<D_DIM / 128, 128>>>(cvec, th_k, vvec);

    dim3 gridD(D_DIM / 128, D_DIM / 128);   // (16, 16)
    dim3 gridB(D_DIM / 128, B_TOK / 128);   // (16, 32)

    // S = src^T @ src   (NT on srcT)
    ntgemm<0, true ><<<gridD, 256, SMEM>>>(srcT, srcT, S, D_DIM, D_DIM, B_TOK,
                                           nullptr, nullptr, nullptr, nullptr, nullptr, 0.f);
    // M = theta_k @ W^T + theta_k - theta_v
    ntgemm<1, true ><<<gridD, 256, SMEM>>>(thkR, WR, Mm, D_DIM, D_DIM, D_DIM,
                                           nullptr, th_k, th_v, nullptr, nullptr, 0.f);
    // T1 = S @ theta_k   (NT with thkT)
    ntgemm<0, false><<<gridD, 256, SMEM>>>(S, thkT, T1, D_DIM, D_DIM, D_DIM,
                                           nullptr, nullptr, nullptr, nullptr, nullptr, 0.f);
    transpose_round<<<dim3(D_DIM / 32, D_DIM / 32), tb>>>(Mm, MT, D_DIM, D_DIM);
    transpose_round<<<dim3(D_DIM / 32, D_DIM / 32), tb>>>(T1, T1T, D_DIM, D_DIM);

    // Wn = W - lr_w * coef * (M^T @ T1 + b (x) v)
    ntgemm<2, true ><<<gridD, 256, SMEM>>>(MT, T1T, Wn, D_DIM, D_DIM, D_DIM,
                                           nullptr, W, lr_w, b, vvec, coef);
    // bn = b - lr_b * coef * (c @ M + B*b)
    bn_kernel<<<D_DIM / 128, 128>>>(Mm, cvec, b, lr_b, bn, coef);

    // P = theta_q @ Wn^T + theta_q
    ntgemm<3, false><<<gridD, 256, SMEM>>>(thqR, Wn, P, D_DIM, D_DIM, D_DIM,
                                           nullptr, th_q, nullptr, nullptr, nullptr, 0.f);
    transpose_round<<<dim3(D_DIM / 32, D_DIM / 32), tb>>>(P, PT, D_DIM, D_DIM);

    // z = src @ P + bn
    ntgemm<4, false><<<gridB, 256, SMEM>>>(srcR, PT, out, B_TOK, D_DIM, D_DIM,
                                           bn, nullptr, nullptr, nullptr, nullptr, 0.f);
}

// round 5
// speedup vs baseline: 4.4086x; 1.1110x over previous
#include <cuda_runtime.h>
#include <cstdint>
#include <math.h>

#define D_DIM 2048
#define B_TOK 4096

// ---------------- scratch (device globals; no allocation allowed) ----------
__device__ float g_srcR[(size_t)B_TOK * D_DIM];
__device__ float g_srcT[(size_t)B_TOK * D_DIM];
__device__ float g_thkR[(size_t)D_DIM * D_DIM];
__device__ float g_thqR[(size_t)D_DIM * D_DIM];
__device__ float g_WR  [(size_t)D_DIM * D_DIM];
__device__ float g_thkT[(size_t)D_DIM * D_DIM];
__device__ float g_S   [(size_t)D_DIM * D_DIM];
__device__ float g_M   [(size_t)D_DIM * D_DIM];
__device__ float g_T1  [(size_t)D_DIM * D_DIM];
__device__ float g_MT  [(size_t)D_DIM * D_DIM];
__device__ float g_T1T [(size_t)D_DIM * D_DIM];
__device__ float g_Wn  [(size_t)D_DIM * D_DIM];
__device__ float g_P   [(size_t)D_DIM * D_DIM];
__device__ float g_PT  [(size_t)D_DIM * D_DIM];
__device__ float g_part[32 * D_DIM];
__device__ float g_c   [D_DIM];
__device__ float g_v   [D_DIM];
__device__ float g_bn  [D_DIM];

// ---------------- PTX helpers ----------------------------------------------
__device__ __forceinline__ float rnd_tf32(float x) {
    uint32_t r;
    asm("cvt.rna.tf32.f32 %0, %1;" : "=r"(r) : "f"(x));
    return __uint_as_float(r);
}

__device__ __forceinline__ void cp16(uint32_t dst, const float* src) {
    asm volatile("cp.async.cg.shared.global [%0], [%1], 16;" :: "r"(dst), "l"(src));
}

__device__ __forceinline__ void ldsm4(uint32_t& r0, uint32_t& r1, uint32_t& r2, uint32_t& r3,
                                      uint32_t addr) {
    asm volatile("ldmatrix.sync.aligned.m8n8.x4.shared.b16 {%0,%1,%2,%3}, [%4];"
                 : "=r"(r0), "=r"(r1), "=r"(r2), "=r"(r3) : "r"(addr));
}

__device__ __forceinline__ void mma_tf32(float c[4], const uint32_t a[4],
                                         uint32_t b0, uint32_t b1) {
    asm volatile(
        "mma.sync.aligned.m16n8k8.row.col.f32.tf32.tf32.f32 "
        "{%0,%1,%2,%3}, {%4,%5,%6,%7}, {%8,%9}, {%0,%1,%2,%3};"
        : "+f"(c[0]), "+f"(c[1]), "+f"(c[2]), "+f"(c[3])
        : "r"(a[0]), "r"(a[1]), "r"(a[2]), "r"(a[3]), "r"(b0), "r"(b1));
}

// ---------------------------------------------------------------------------
// NT tf32 tensor GEMM:  C[M,N] = A[M,K] * B[N,K]^T  (+ fused epilogues)
// Inputs MUST be pre-rounded to tf32 (RNA) — mainloop has no cvt.
// CTA 128x128, BK=32, 4-stage cp.async, 8 warps of 64x32, ldmatrix frags with
// cross-kk double buffering, one barrier per k-tile.
// EPI 0: C = acc
// EPI 1: C = acc + e1[idx] - e2[idx]
// EPI 2: C = e1[idx] - e2[idx] * coef * (acc + ev0[row]*ev1[col])
// EPI 3: C = acc + e1[idx]
// EPI 4: C = acc + e0[col]
// SYM: C symmetric (A==B); grid.x = 136 lower-triangle tiles; mirror blocks.
// ---------------------------------------------------------------------------
template <int EPI, bool RND, bool SYM>
__global__ void __launch_bounds__(256)
ntgemm(const float* __restrict__ A, const float* __restrict__ B,
       float* __restrict__ C, int M, int N, int K,
       const float* __restrict__ e0, const float* __restrict__ e1,
       const float* __restrict__ e2, const float* __restrict__ ev0,
       const float* __restrict__ ev1, float coef)
{
    constexpr int BK   = 32;
    constexpr int TILE = 128 * BK * 4;   // 16 KB per operand tile
    constexpr int SS   = 2 * TILE;       // 32 KB per stage

    extern __shared__ __align__(128) char smraw[];
    const uint32_t sb = (uint32_t)__cvta_generic_to_shared(smraw);

    const int tid  = threadIdx.x;
    const int lane = tid & 31;
    const int wid  = tid >> 5;
    const int wm   = (wid & 1) * 64;
    const int wn   = (wid >> 1) * 32;

    int bx, by;
    if (SYM) {
        const int i = blockIdx.x;
        int e = (int)((sqrtf(8.0f * (float)i + 1.0f) - 1.0f) * 0.5f);
        while ((e + 1) * (e + 2) / 2 <= i) ++e;
        while (e * (e + 1) / 2 > i) --e;
        by = e;
        bx = i - e * (e + 1) / 2;
    } else {
        bx = blockIdx.x;
        by = blockIdx.y;
    }
    const int m0 = by * 128;
    const int n0 = bx * 128;

    // ---- global->smem loader mapping (XOR-swizzled 16B chunks) ----
    const int lr = tid >> 3;            // 0..31 (row base; +32*i)
    const int lc = tid & 7;             // chunk 0..7
    const uint32_t lOff = (uint32_t)(lr * 128 + ((lc ^ (lr & 7)) << 4));
    const float* aG = A + (size_t)(m0 + lr) * K + lc * 4;
    const float* bG = B + (size_t)(n0 + lr) * K + lc * 4;

    auto loadTile = [&](int t) {
        const uint32_t base = sb + (uint32_t)((t & 3) * SS);
        const float* a = aG + (size_t)t * BK;
        const float* b = bG + (size_t)t * BK;
#pragma unroll
        for (int i = 0; i < 4; ++i)
            cp16(base + lOff + 4096u * i, a + (size_t)(32 * i) * K);
#pragma unroll
        for (int i = 0; i < 4; ++i)
            cp16(base + TILE + lOff + 4096u * i, b + (size_t)(32 * i) * K);
        asm volatile("cp.async.commit_group;" ::: "memory");
    };

    // ---- ldmatrix addressing (precomputed) ----
    const int rr  = lane & 7;
    const int loA = (lane >> 3) & 1;
    const int hiA = (lane >> 4) & 1;
    const int loB = (lane >> 4) & 1;
    const int hiB = (lane >> 3) & 1;
    const uint32_t swz = (uint32_t)rr << 4;

    uint32_t aRow[4], bRow[2];
#pragma unroll
    for (int mf = 0; mf < 4; ++mf)
        aRow[mf] = (uint32_t)((wm + mf * 16 + loA * 8 + rr) * 128);
#pragma unroll
    for (int nfp = 0; nfp < 2; ++nfp)
        bRow[nfp] = (uint32_t)((wn + nfp * 16 + loB * 8 + rr) * 128);

    float acc[4][4][4];
#pragma unroll
    for (int i = 0; i < 4; ++i)
#pragma unroll
        for (int j = 0; j < 4; ++j)
#pragma unroll
            for (int k = 0; k < 4; ++k) acc[i][j][k] = 0.0f;

    const int nt = K / BK;
    loadTile(0);
    loadTile(1);
    loadTile(2);

    uint32_t af[2][4][4];
    uint32_t bf[2][2][4];

    for (int t = 0; t < nt; ++t) {
        if (t + 3 < nt) {
            loadTile(t + 3);
            asm volatile("cp.async.wait_group 3;" ::: "memory");
        } else if (t + 2 < nt) {
            asm volatile("cp.async.wait_group 2;" ::: "memory");
        } else if (t + 1 < nt) {
            asm volatile("cp.async.wait_group 1;" ::: "memory");
        } else {
            asm volatile("cp.async.wait_group 0;" ::: "memory");
        }
        __syncthreads();

        const uint32_t stA = sb + (uint32_t)((t & 3) * SS);
        const uint32_t stB = stA + TILE;

        // prefetch kk=0 fragments
        {
            const uint32_t ak = (((uint32_t)hiA) << 4) ^ swz;
            const uint32_t bk = (((uint32_t)hiB) << 4) ^ swz;
#pragma unroll
            for (int mf = 0; mf < 4; ++mf)
                ldsm4(af[0][mf][0], af[0][mf][1], af[0][mf][2], af[0][mf][3],
                      stA + aRow[mf] + ak);
#pragma unroll
            for (int nfp = 0; nfp < 2; ++nfp)
                ldsm4(bf[0][nfp][0], bf[0][nfp][1], bf[0][nfp][2], bf[0][nfp][3],
                      stB + bRow[nfp] + bk);
        }

#pragma unroll
        for (int kk = 0; kk < 4; ++kk) {
            const int cur = kk & 1;
            if (kk < 3) {
                const int nxt = cur ^ 1;
                const uint32_t ak = (((uint32_t)(2 * (kk + 1) + hiA)) << 4) ^ swz;
                const uint32_t bk = (((uint32_t)(2 * (kk + 1) + hiB)) << 4) ^ swz;
#pragma unroll
                for (int mf = 0; mf < 4; ++mf)
                    ldsm4(af[nxt][mf][0], af[nxt][mf][1], af[nxt][mf][2], af[nxt][mf][3],
                          stA + aRow[mf] + ak);
#pragma unroll
                for (int nfp = 0; nfp < 2; ++nfp)
                    ldsm4(bf[nxt][nfp][0], bf[nxt][nfp][1], bf[nxt][nfp][2], bf[nxt][nfp][3],
                          stB + bRow[nfp] + bk);
            }
#pragma unroll
            for (int mf = 0; mf < 4; ++mf)
#pragma unroll
                for (int nf = 0; nf < 4; ++nf)
                    mma_tf32(acc[mf][nf], af[cur][mf],
                             bf[cur][nf >> 1][(nf & 1) * 2],
                             bf[cur][nf >> 1][(nf & 1) * 2 + 1]);
        }
    }

    // ---- epilogue ----
    const int g   = lane >> 2;
    const int tig = lane & 3;
#pragma unroll
    for (int mf = 0; mf < 4; ++mf) {
#pragma unroll
        for (int nf = 0; nf < 4; ++nf) {
#pragma unroll
            for (int h = 0; h < 2; ++h) {
                const int r = m0 + wm + mf * 16 + g + h * 8;
                const int c = n0 + wn + nf * 8 + 2 * tig;
                const size_t idx = (size_t)r * N + c;
                float v0 = acc[mf][nf][h * 2 + 0];
                float v1 = acc[mf][nf][h * 2 + 1];
                if (EPI == 1) {
                    const float2 a1 = *reinterpret_cast<const float2*>(e1 + idx);
                    const float2 a2 = *reinterpret_cast<const float2*>(e2 + idx);
                    v0 += a1.x - a2.x;
                    v1 += a1.y - a2.y;
                } else if (EPI == 2) {
                    const float2 w  = *reinterpret_cast<const float2*>(e1 + idx);
                    const float2 lr = *reinterpret_cast<const float2*>(e2 + idx);
                    const float bi  = ev0[r];
                    const float g0  = coef * (v0 + bi * ev1[c]);
                    const float g1  = coef * (v1 + bi * ev1[c + 1]);
                    v0 = w.x - lr.x * g0;
                    v1 = w.y - lr.y * g1;
                } else if (EPI == 3) {
                    const float2 a1 = *reinterpret_cast<const float2*>(e1 + idx);
                    v0 += a1.x;
                    v1 += a1.y;
                } else if (EPI == 4) {
                    v0 += e0[c];
                    v1 += e0[c + 1];
                }
                if (RND) { v0 = rnd_tf32(v0); v1 = rnd_tf32(v1); }
                float2 out; out.x = v0; out.y = v1;
                *reinterpret_cast<float2*>(C + idx) = out;
            }
        }
    }

    // ---- symmetric mirror: write block (bx, by) = transpose of this block ----
    if (SYM && bx != by) {
        __syncthreads();
        float* esm = reinterpret_cast<float*>(smraw);   // 128 x 132 staging
#pragma unroll
        for (int mf = 0; mf < 4; ++mf) {
#pragma unroll
            for (int nf = 0; nf < 4; ++nf) {
#pragma unroll
                for (int h = 0; h < 2; ++h) {
                    const int rl = wm + mf * 16 + g + h * 8;
                    const int cl = wn + nf * 8 + 2 * tig;
                    float v0 = acc[mf][nf][h * 2 + 0];
                    float v1 = acc[mf][nf][h * 2 + 1];
                    if (RND) { v0 = rnd_tf32(v0); v1 = rnd_tf32(v1); }
                    esm[(cl + 0) * 132 + rl] = v0;
                    esm[(cl + 1) * 132 + rl] = v1;
                }
            }
        }
        __syncthreads();
#pragma unroll
        for (int i = 0; i < 16; ++i) {
            const int chunk = tid + (i << 8);
            const int row  = chunk >> 5;          // 0..127
            const int col4 = (chunk & 31) << 2;   // 0..124
            const float4 v = *reinterpret_cast<const float4*>(esm + row * 132 + col4);
            *reinterpret_cast<float4*>(C + (size_t)(n0 + row) * N + m0 + col4) = v;
        }
    }
}

// ---------------- small kernels ----------------------------------------------
__global__ void round_kernel(const float* __restrict__ in, float* __restrict__ out, int n4)
{
    int i = blockIdx.x * blockDim.x + threadIdx.x;
    if (i < n4) {
        float4 v = reinterpret_cast<const float4*>(in)[i];
        v.x = rnd_tf32(v.x); v.y = rnd_tf32(v.y);
        v.z = rnd_tf32(v.z); v.w = rnd_tf32(v.w);
        reinterpret_cast<float4*>(out)[i] = v;
    }
}

// out[c, r] = rnd(in[r, c]); in is [R, C]; grid (C/32, R/32), block (32, 8)
__global__ void transpose_round(const float* __restrict__ in, float* __restrict__ out,
                                int R, int C)
{
    __shared__ float tile[32][33];
    const int bx = blockIdx.x * 32, by = blockIdx.y * 32;
    const int x = threadIdx.x, y = threadIdx.y;
#pragma unroll
    for (int j = 0; j < 32; j += 8)
        tile[y + j][x] = in[(size_t)(by + y + j) * C + bx + x];
    __syncthreads();
#pragma unroll
    for (int j = 0; j < 32; j += 8)
        out[(size_t)(bx + y + j) * R + by + x] = rnd_tf32(tile[x][y + j]);
}

// partial column sums over 128-row chunks (src is [4096, 2048])
__global__ void colsum_kernel(const float* __restrict__ in, float* __restrict__ part)
{
    int col = blockIdx.x * blockDim.x + threadIdx.x;
    int chunk = blockIdx.y;
    const float* p = in + (size_t)chunk * 128 * D_DIM + col;
    float s0 = 0.f, s1 = 0.f, s2 = 0.f, s3 = 0.f;
#pragma unroll
    for (int r = 0; r < 128; r += 4) {
        s0 += p[(size_t)(r + 0) * D_DIM];
        s1 += p[(size_t)(r + 1) * D_DIM];
        s2 += p[(size_t)(r + 2) * D_DIM];
        s3 += p[(size_t)(r + 3) * D_DIM];
    }
    part[chunk * D_DIM + col] = (s0 + s1) + (s2 + s3);
}

__global__ void creduce_kernel(const float* __restrict__ part, float* __restrict__ c)
{
    int j = blockIdx.x * blockDim.x + threadIdx.x;
    float s = 0.f;
#pragma unroll
    for (int ch = 0; ch < 32; ++ch) s += part[ch * D_DIM + j];
    c[j] = s;
}

// outv[j] = sum_k vec[k] * Mat[k, j]
__global__ void vecmat_kernel(const float* __restrict__ vec, const float* __restrict__ Mat,
                              float* __restrict__ outv)
{
    int j = blockIdx.x * blockDim.x + threadIdx.x;
    float s0 = 0.f, s1 = 0.f, s2 = 0.f, s3 = 0.f;
#pragma unroll 4
    for (int k = 0; k < D_DIM; k += 4) {
        s0 += vec[k + 0] * Mat[(size_t)(k + 0) * D_DIM + j];
        s1 += vec[k + 1] * Mat[(size_t)(k + 1) * D_DIM + j];
        s2 += vec[k + 2] * Mat[(size_t)(k + 2) * D_DIM + j];
        s3 += vec[k + 3] * Mat[(size_t)(k + 3) * D_DIM + j];
    }
    outv[j] = (s0 + s1) + (s2 + s3);
}

// bn[j] = b[j] - lr_b[j] * coef * ( (c @ M)[j] + B_TOK * b[j] )
__global__ void bn_kernel(const float* __restrict__ Mm, const float* __restrict__ c,
                          const float* __restrict__ b, const float* __restrict__ lrb,
                          float* __restrict__ bn, float coef)
{
    int j = blockIdx.x * blockDim.x + threadIdx.x;
    float s0 = 0.f, s1 = 0.f, s2 = 0.f, s3 = 0.f;
#pragma unroll 4
    for (int k = 0; k < D_DIM; k += 4) {
        s0 += c[k + 0] * Mm[(size_t)(k + 0) * D_DIM + j];
        s1 += c[k + 1] * Mm[(size_t)(k + 1) * D_DIM + j];
        s2 += c[k + 2] * Mm[(size_t)(k + 2) * D_DIM + j];
        s3 += c[k + 3] * Mm[(size_t)(k + 3) * D_DIM + j];
    }
    float s = (s0 + s1) + (s2 + s3);
    bn[j] = b[j] - lrb[j] * coef * (s + (float)B_TOK * b[j]);
}

// ---------------- host --------------------------------------------------------
extern "C" void kernel_launch(void* const* d_in, const int* in_sizes, int n_in,
                              void* d_out, int out_size)
{
    const float* src  = (const float*)d_in[0];
    const float* th_k = (const float*)d_in[1];
    const float* th_q = (const float*)d_in[2];
    const float* th_v = (const float*)d_in[3];
    const float* W    = (const float*)d_in[4];
    const float* b    = (const float*)d_in[5];
    const float* lr_w = (const float*)d_in[6];
    const float* lr_b = (const float*)d_in[7];
    float* out = (float*)d_out;

    float *srcR, *srcT, *thkR, *thqR, *WR, *thkT, *S, *Mm, *T1, *MT, *T1T, *Wn, *P, *PT;
    float *part, *cvec, *vvec, *bn;
    cudaGetSymbolAddress((void**)&srcR, g_srcR);
    cudaGetSymbolAddress((void**)&srcT, g_srcT);
    cudaGetSymbolAddress((void**)&thkR, g_thkR);
    cudaGetSymbolAddress((void**)&thqR, g_thqR);
    cudaGetSymbolAddress((void**)&WR,   g_WR);
    cudaGetSymbolAddress((void**)&thkT, g_thkT);
    cudaGetSymbolAddress((void**)&S,    g_S);
    cudaGetSymbolAddress((void**)&Mm,   g_M);
    cudaGetSymbolAddress((void**)&T1,   g_T1);
    cudaGetSymbolAddress((void**)&MT,   g_MT);
    cudaGetSymbolAddress((void**)&T1T,  g_T1T);
    cudaGetSymbolAddress((void**)&Wn,   g_Wn);
    cudaGetSymbolAddress((void**)&P,    g_P);
    cudaGetSymbolAddress((void**)&PT,   g_PT);
    cudaGetSymbolAddress((void**)&part, g_part);
    cudaGetSymbolAddress((void**)&cvec, g_c);
    cudaGetSymbolAddress((void**)&vvec, g_v);
    cudaGetSymbolAddress((void**)&bn,   g_bn);

    const float coef = 2.0f / ((float)B_TOK * (float)D_DIM);
    const int SMEM = 4 * 2 * 128 * 32 * 4;   // 131072

    cudaFuncSetAttribute(ntgemm<0, true,  true >, cudaFuncAttributeMaxDynamicSharedMemorySize, SMEM);
    cudaFuncSetAttribute(ntgemm<0, false, false>, cudaFuncAttributeMaxDynamicSharedMemorySize, SMEM);
    cudaFuncSetAttribute(ntgemm<1, true,  false>, cudaFuncAttributeMaxDynamicSharedMemorySize, SMEM);
    cudaFuncSetAttribute(ntgemm<2, true,  false>, cudaFuncAttributeMaxDynamicSharedMemorySize, SMEM);
    cudaFuncSetAttribute(ntgemm<3, false, false>, cudaFuncAttributeMaxDynamicSharedMemorySize, SMEM);
    cudaFuncSetAttribute(ntgemm<4, false, false>, cudaFuncAttributeMaxDynamicSharedMemorySize, SMEM);

    dim3 tb(32, 8);

    // prep: rounded copies + transposes (transpose_round also rounds)
    round_kernel<<<(B_TOK * D_DIM / 4 + 255) / 256, 256>>>(src, srcR, B_TOK * D_DIM / 4);
    round_kernel<<<(D_DIM * D_DIM / 4 + 255) / 256, 256>>>(th_k, thkR, D_DIM * D_DIM / 4);
    round_kernel<<<(D_DIM * D_DIM / 4 + 255) / 256, 256>>>(th_q, thqR, D_DIM * D_DIM / 4);
    round_kernel<<<(D_DIM * D_DIM / 4 + 255) / 256, 256>>>(W, WR, D_DIM * D_DIM / 4);
    transpose_round<<<dim3(D_DIM / 32, B_TOK / 32), tb>>>(src, srcT, B_TOK, D_DIM);
    transpose_round<<<dim3(D_DIM / 32, D_DIM / 32), tb>>>(th_k, thkT, D_DIM, D_DIM);

    // column sums of src -> c ; v = c @ theta_k
    colsum_kernel<<<dim3(D_DIM / 256, 32), 256>>>(src, part);
    creduce_kernel<<<D_DIM / 256, 256>>>(part, cvec);
    vecmat_kernel<<<D_DIM / 128, 128>>>(cvec, th_k, vvec);

    dim3 gridD(D_DIM / 128, D_DIM / 128);   // (16, 16)
    dim3 gridB(D_DIM / 128, B_TOK / 128);   // (16, 32)
    const int nSymTiles = (D_DIM / 128) * (D_DIM / 128 + 1) / 2;   // 136

    // S = src^T @ src   (symmetric: lower-triangle tiles + mirror)
    ntgemm<0, true,  true ><<<nSymTiles, 256, SMEM>>>(srcT, srcT, S, D_DIM, D_DIM, B_TOK,
                                                      nullptr, nullptr, nullptr, nullptr, nullptr, 0.f);
    // M = theta_k @ W^T + theta_k - theta_v
    ntgemm<1, true,  false><<<gridD, 256, SMEM>>>(thkR, WR, Mm, D_DIM, D_DIM, D_DIM,
                                                  nullptr, th_k, th_v, nullptr, nullptr, 0.f);
    // T1 = S @ theta_k   (NT with thkT)
    ntgemm<0, false, false><<<gridD, 256, SMEM>>>(S, thkT, T1, D_DIM, D_DIM, D_DIM,
                                                  nullptr, nullptr, nullptr, nullptr, nullptr, 0.f);
    transpose_round<<<dim3(D_DIM / 32, D_DIM / 32), tb>>>(Mm, MT, D_DIM, D_DIM);
    transpose_round<<<dim3(D_DIM / 32, D_DIM / 32), tb>>>(T1, T1T, D_DIM, D_DIM);

    // Wn = W - lr_w * coef * (M^T @ T1 + b (x) v)
    ntgemm<2, true,  false><<<gridD, 256, SMEM>>>(MT, T1T, Wn, D_DIM, D_DIM, D_DIM,
                                                  nullptr, W, lr_w, b, vvec, coef);
    // bn = b - lr_b * coef * (c @ M + B*b)
    bn_kernel<<<D_DIM / 128, 128>>>(Mm, cvec, b, lr_b, bn, coef);

    // P = theta_q @ Wn^T + theta_q
    ntgemm<3, false, false><<<gridD, 256, SMEM>>>(thqR, Wn, P, D_DIM, D_DIM, D_DIM,
                                                  nullptr, th_q, nullptr, nullptr, nullptr, 0.f);
    transpose_round<<<dim3(D_DIM / 32, D_DIM / 32), tb>>>(P, PT, D_DIM, D_DIM);

    // z = src @ P + bn
    ntgemm<4, false, false><<<gridB, 256, SMEM>>>(srcR, PT, out, B_TOK, D_DIM, D_DIM,
                                                  bn, nullptr, nullptr, nullptr, nullptr, 0.f);
}